// round 7
// baseline (speedup 1.0000x reference)
#include <cuda_runtime.h>
#include <math.h>

#define N 384
#define D 128
#define TPB 768            // 2 threads per j: thread t -> j = t % 384, k-half = t / 384
#define NWARP (TPB / 32)   // 24
#define FULL 0xFFFFFFFFu

// Persistent accumulators. Zero at load; last block resets after finalizing so
// every invocation (correctness run + each graph replay) starts clean.
__device__ double   g_acc_trans = 0.0;
__device__ double   g_acc_hard  = 0.0;
__device__ unsigned g_done      = 0u;

__global__ __launch_bounds__(TPB) void rnc_main_kernel(
    const float* __restrict__ feat,   // [N, D]
    const float* __restrict__ rgreen, // [N, 3]
    const float* __restrict__ rred,   // [N, 3]
    const float* __restrict__ trans,  // [N, 3]
    const int*   __restrict__ sym,    // [N, 1]
    float*       __restrict__ out)
{
    __shared__ __align__(16) float fi[D];
    __shared__ __align__(16) float sq_sh[N];
    __shared__ __align__(16) float td_sh[N];
    __shared__ __align__(16) float rd_sh[N];
    __shared__ __align__(16) float e_sh[N];
    __shared__ __align__(16) float l_sh[N];
    __shared__ __align__(16) float pdent[TPB];
    __shared__ __align__(16) float pdenh[TPB];
    __shared__ double redt[NWARP];
    __shared__ double redh[NWARP];

    const int i    = blockIdx.x;
    const int tid  = threadIdx.x;
    const int lane = tid & 31;
    const int w    = tid >> 5;
    const bool hi  = tid >= N;        // upper k-half thread
    const int j    = hi ? tid - N : tid;

    // ---- stage row-i feature vector in shared (coalesced) ----
    if (tid < D / 4)
        reinterpret_cast<float4*>(fi)[tid] =
            reinterpret_cast<const float4*>(feat + i * D)[tid];
    __syncthreads();

    // ---- feature squared distances: 24 warps x 16 rows each, coalesced ----
    {
        const float4 a = reinterpret_cast<const float4*>(fi)[lane];
        const int rowbase = w * 16;
        #pragma unroll 4
        for (int r = 0; r < 16; r++) {
            float4 b = reinterpret_cast<const float4*>(feat + (rowbase + r) * D)[lane];
            float d0 = a.x - b.x, d1 = a.y - b.y, d2 = a.z - b.z, d3 = a.w - b.w;
            float p = d0 * d0;
            p = fmaf(d1, d1, p);
            p = fmaf(d2, d2, p);
            p = fmaf(d3, d3, p);
            #pragma unroll
            for (int o = 16; o; o >>= 1) p += __shfl_xor_sync(FULL, p, o);
            if (lane == r) sq_sh[rowbase + r] = p;
        }
    }

    // ---- label diffs + logits/exp for column j: lower 384 threads only ----
    if (!hi) {
        // trans smooth-L1 (beta=1), mean over 3 coords
        float ti0 = trans[i*3+0], ti1 = trans[i*3+1], ti2 = trans[i*3+2]; // broadcast
        float d0 = ti0 - trans[j*3+0];
        float d1 = ti1 - trans[j*3+1];
        float d2 = ti2 - trans[j*3+2];
        float a0 = fabsf(d0), a1 = fabsf(d1), a2 = fabsf(d2);
        float s = ((a0 < 1.f) ? 0.5f*d0*d0 : a0 - 0.5f)
                + ((a1 < 1.f) ? 0.5f*d1*d1 : a1 - 0.5f)
                + ((a2 < 1.f) ? 0.5f*d2*d2 : a2 - 0.5f);
        td_sh[j] = s * (1.0f / 3.0f);

        // rot cosine diffs + sym gating
        const float EPSC = 1e-8f;
        float gi0 = rgreen[i*3+0], gi1 = rgreen[i*3+1], gi2 = rgreen[i*3+2];
        float ngi = fmaxf(sqrtf(gi0*gi0 + gi1*gi1 + gi2*gi2), EPSC);
        float gj0 = rgreen[j*3+0], gj1 = rgreen[j*3+1], gj2 = rgreen[j*3+2];
        float ngj = fmaxf(sqrtf(gj0*gj0 + gj1*gj1 + gj2*gj2), EPSC);
        float gd  = 1.0f - (gi0*gj0 + gi1*gj1 + gi2*gj2) / (ngi * ngj);

        float ri0 = rred[i*3+0], ri1 = rred[i*3+1], ri2 = rred[i*3+2];
        float nri = fmaxf(sqrtf(ri0*ri0 + ri1*ri1 + ri2*ri2), EPSC);
        float rj0 = rred[j*3+0], rj1 = rred[j*3+1], rj2 = rred[j*3+2];
        float nrj = fmaxf(sqrtf(rj0*rj0 + rj1*rj1 + rj2*rj2), EPSC);
        float rdd = 1.0f - (ri0*rj0 + ri1*rj1 + ri2*rj2) / (nri * nrj);

        bool psym = (sym[i] == 1) || (sym[j] == 1);
        rd_sh[j] = psym ? gd : gd + rdd;
    }
    __syncthreads();

    // logits: rowmax is exactly 0 (logit_ii = -0.5*sqrt(0) bit-exactly, all
    // others <= 0), so no max-subtraction pass is needed.
    if (!hi) {
        float sq = sq_sh[j];
        float l  = -((sq > 0.f) ? sqrtf(sq) : 0.f) * 0.5f;
        l_sh[j] = l;
        e_sh[j] = (j == i) ? 0.f : expf(l);  // zero diag weight == offdiag einsum
    }
    __syncthreads();

    // ---- masked denominators over this thread's k-half (192 k, 48 float4) ----
    const float tij = td_sh[j];
    const float rij = rd_sh[j];
    float dent = 0.f, denh = 0.f;
    {
        const int k4base = hi ? (N / 8) : 0;  // 48 float4 groups per half
        const float4* td4 = reinterpret_cast<const float4*>(td_sh) + k4base;
        const float4* rd4 = reinterpret_cast<const float4*>(rd_sh) + k4base;
        const float4* e4  = reinterpret_cast<const float4*>(e_sh)  + k4base;
        #pragma unroll 4
        for (int k4 = 0; k4 < N / 8; k4++) {
            float4 tk = td4[k4];
            float4 rk = rd4[k4];
            float4 ek = e4[k4];
            if (tij <= tk.x) { dent += ek.x; if (rij <= rk.x) denh += ek.x; }
            if (tij <= tk.y) { dent += ek.y; if (rij <= rk.y) denh += ek.y; }
            if (tij <= tk.z) { dent += ek.z; if (rij <= rk.z) denh += ek.z; }
            if (tij <= tk.w) { dent += ek.w; if (rij <= rk.w) denh += ek.w; }
        }
    }
    pdent[tid] = dent;
    pdenh[tid] = denh;
    __syncthreads();

    // ---- combine halves + per-j log terms (lower 384 threads) ----
    double pos_t = 0.0, pos_h = 0.0;
    if (!hi && j != i) {
        float dt = pdent[j] + pdent[j + N];
        float dh = pdenh[j] + pdenh[j + N];
        float l  = l_sh[j];
        pos_t = (double)(l - logf(dt + 1e-7f));
        pos_h = (double)(l - logf(dh + 1e-7f));
    }

    // ---- block reduction (double) ----
    #pragma unroll
    for (int o = 16; o; o >>= 1) {
        pos_t += __shfl_xor_sync(FULL, pos_t, o);
        pos_h += __shfl_xor_sync(FULL, pos_h, o);
    }
    if (lane == 0) { redt[w] = pos_t; redh[w] = pos_h; }
    __syncthreads();

    // ---- global accumulation + last-block finalize (self-resetting) ----
    if (tid == 0) {
        double at = 0.0, ah = 0.0;
        #pragma unroll
        for (int ww = 0; ww < NWARP / 2; ww++) { at += redt[ww]; ah += redh[ww]; }
        atomicAdd(&g_acc_trans, at);
        atomicAdd(&g_acc_hard,  ah);
        __threadfence();
        unsigned ticket = atomicAdd(&g_done, 1u);
        if (ticket == (unsigned)(gridDim.x - 1)) {
            double vt = atomicAdd(&g_acc_trans, 0.0);
            double vh = atomicAdd(&g_acc_hard,  0.0);
            const double denom = (double)N * (double)(N - 1);
            out[0] = (float)((-vh / denom) + 0.5 * (-vt / denom));
            g_acc_trans = 0.0;
            g_acc_hard  = 0.0;
            g_done      = 0u;
        }
    }
}

extern "C" void kernel_launch(void* const* d_in, const int* in_sizes, int n_in,
                              void* d_out, int out_size) {
    const float* feat   = (const float*)d_in[0];
    const float* rgreen = (const float*)d_in[1];
    const float* rred   = (const float*)d_in[2];
    const float* trans  = (const float*)d_in[3];
    const int*   sym    = (const int*)d_in[4];
    float* out = (float*)d_out;

    rnc_main_kernel<<<N, TPB>>>(feat, rgreen, rred, trans, sym, out);
}

// round 8
// speedup vs baseline: 1.0650x; 1.0650x over previous
#include <cuda_runtime.h>
#include <math.h>

#define N 384
#define HALF 192
#define TPB 192            // 6 warps; thread t owns j0=t, j1=t+192; k-half per block
#define NWARP (TPB / 32)
#define FULL 0xFFFFFFFFu

// Persistent accumulators / scratch. Zero at load; every ticket/accumulator is
// reset by its last user, so each invocation (correctness run + every graph
// replay) starts clean. Written-before-read scratch needs no init.
__device__ double   g_acc_trans = 0.0;
__device__ double   g_acc_hard  = 0.0;
__device__ unsigned g_done      = 0u;
__device__ unsigned g_row_ticket[N];          // zero-init; reset after each use
__device__ float    g_pdent[2][N][N];         // partial dent per k-half
__device__ float    g_pdenh[2][N][N];         // partial denh per k-half
__device__ float    g_l[N][N];                // logits (rowmax==0 exactly)

__global__ __launch_bounds__(TPB) void rnc_main_kernel(
    const float* __restrict__ feat,   // [N, D=128]
    const float* __restrict__ rgreen, // [N, 3]
    const float* __restrict__ rred,   // [N, 3]
    const float* __restrict__ trans,  // [N, 3]
    const int*   __restrict__ sym,    // [N, 1]
    float*       __restrict__ out)
{
    __shared__ __align__(16) float fi[128];
    __shared__ __align__(16) float td_sh[N];
    __shared__ __align__(16) float rd_sh[N];
    __shared__ __align__(16) float e_sh[HALF];
    __shared__ double redt[NWARP];
    __shared__ double redh[NWARP];
    __shared__ int    s_combine;

    const int i    = blockIdx.x >> 1;
    const int h    = blockIdx.x & 1;      // k-half this block owns
    const int tid  = threadIdx.x;
    const int lane = tid & 31;
    const int w    = tid >> 5;
    const int j0   = tid;
    const int j1   = tid + HALF;

    // ---- stage row-i feature vector (coalesced) ----
    if (tid < 32)
        reinterpret_cast<float4*>(fi)[tid] =
            reinterpret_cast<const float4*>(feat + i * 128)[tid];
    __syncthreads();

    // ---- sq / logit / e for THIS half's 192 k-rows (warp-coop, coalesced) ----
    {
        const float4 a = reinterpret_cast<const float4*>(fi)[lane];
        const int rowbase = h * HALF + w * 32;   // global row of lane r is rowbase+r
        float sq = 0.f;
        #pragma unroll 4
        for (int r = 0; r < 32; r++) {
            float4 b = reinterpret_cast<const float4*>(feat + (rowbase + r) * 128)[lane];
            float d0 = a.x - b.x, d1 = a.y - b.y, d2 = a.z - b.z, d3 = a.w - b.w;
            float p = d0 * d0;
            p = fmaf(d1, d1, p);
            p = fmaf(d2, d2, p);
            p = fmaf(d3, d3, p);
            #pragma unroll
            for (int o = 16; o; o >>= 1) p += __shfl_xor_sync(FULL, p, o);
            if (lane == r) sq = p;
        }
        // rowmax of logits is exactly 0 (logit_ii = -0.5*sqrt(0) bit-exactly,
        // all others <= 0) -> no max pass needed.
        int rg = rowbase + lane;                  // this thread's global row
        float l = -((sq > 0.f) ? sqrtf(sq) : 0.f) * 0.5f;
        e_sh[w * 32 + lane] = (rg == i) ? 0.f : expf(l);  // zero diag == offdiag
        g_l[i][rg] = l;
    }

    // ---- label diffs for j0 and j1 (full j-range; cheap, duplicated per half) ----
    {
        float ti0 = trans[i*3+0], ti1 = trans[i*3+1], ti2 = trans[i*3+2]; // bcast
        const float EPSC = 1e-8f;
        float gi0 = rgreen[i*3+0], gi1 = rgreen[i*3+1], gi2 = rgreen[i*3+2];
        float ngi = fmaxf(sqrtf(gi0*gi0 + gi1*gi1 + gi2*gi2), EPSC);
        float ri0 = rred[i*3+0], ri1 = rred[i*3+1], ri2 = rred[i*3+2];
        float nri = fmaxf(sqrtf(ri0*ri0 + ri1*ri1 + ri2*ri2), EPSC);
        int   si  = sym[i];
        #pragma unroll
        for (int hh = 0; hh < 2; hh++) {
            int j = hh ? j1 : j0;
            float d0 = ti0 - trans[j*3+0];
            float d1 = ti1 - trans[j*3+1];
            float d2 = ti2 - trans[j*3+2];
            float a0 = fabsf(d0), a1 = fabsf(d1), a2 = fabsf(d2);
            float s = ((a0 < 1.f) ? 0.5f*d0*d0 : a0 - 0.5f)
                    + ((a1 < 1.f) ? 0.5f*d1*d1 : a1 - 0.5f)
                    + ((a2 < 1.f) ? 0.5f*d2*d2 : a2 - 0.5f);
            td_sh[j] = s * (1.0f / 3.0f);

            float gj0 = rgreen[j*3+0], gj1 = rgreen[j*3+1], gj2 = rgreen[j*3+2];
            float ngj = fmaxf(sqrtf(gj0*gj0 + gj1*gj1 + gj2*gj2), EPSC);
            float gd  = 1.0f - (gi0*gj0 + gi1*gj1 + gi2*gj2) / (ngi * ngj);
            float rj0 = rred[j*3+0], rj1 = rred[j*3+1], rj2 = rred[j*3+2];
            float nrj = fmaxf(sqrtf(rj0*rj0 + rj1*rj1 + rj2*rj2), EPSC);
            float rdd = 1.0f - (ri0*rj0 + ri1*rj1 + ri2*rj2) / (nri * nrj);
            bool psym = (si == 1) || (sym[j] == 1);
            rd_sh[j] = psym ? gd : gd + rdd;
        }
    }
    __syncthreads();

    // ---- masked partial denominators over this block's 192-k half ----
    const float td0 = td_sh[j0], td1 = td_sh[j1];
    const float rd0 = rd_sh[j0], rd1 = rd_sh[j1];
    float dent0 = 0.f, denh0 = 0.f, dent1 = 0.f, denh1 = 0.f;
    {
        const float4* td4 = reinterpret_cast<const float4*>(td_sh) + h * (HALF / 4);
        const float4* rd4 = reinterpret_cast<const float4*>(rd_sh) + h * (HALF / 4);
        const float4* e4  = reinterpret_cast<const float4*>(e_sh);
        #pragma unroll 4
        for (int k4 = 0; k4 < HALF / 4; k4++) {
            float4 tk = td4[k4];
            float4 rk = rd4[k4];
            float4 ek = e4[k4];
            if (td0 <= tk.x) { dent0 += ek.x; if (rd0 <= rk.x) denh0 += ek.x; }
            if (td0 <= tk.y) { dent0 += ek.y; if (rd0 <= rk.y) denh0 += ek.y; }
            if (td0 <= tk.z) { dent0 += ek.z; if (rd0 <= rk.z) denh0 += ek.z; }
            if (td0 <= tk.w) { dent0 += ek.w; if (rd0 <= rk.w) denh0 += ek.w; }
            if (td1 <= tk.x) { dent1 += ek.x; if (rd1 <= rk.x) denh1 += ek.x; }
            if (td1 <= tk.y) { dent1 += ek.y; if (rd1 <= rk.y) denh1 += ek.y; }
            if (td1 <= tk.z) { dent1 += ek.z; if (rd1 <= rk.z) denh1 += ek.z; }
            if (td1 <= tk.w) { dent1 += ek.w; if (rd1 <= rk.w) denh1 += ek.w; }
        }
    }
    g_pdent[h][i][j0] = dent0;  g_pdent[h][i][j1] = dent1;
    g_pdenh[h][i][j0] = denh0;  g_pdenh[h][i][j1] = denh1;

    // ---- per-row rendezvous: second-arriving half-block combines ----
    __threadfence();
    __syncthreads();
    if (tid == 0) s_combine = (atomicAdd(&g_row_ticket[i], 1u) == 1u) ? 1 : 0;
    __syncthreads();
    if (!s_combine) return;
    __threadfence();   // acquire: make the other half's writes visible

    double pos_t = 0.0, pos_h = 0.0;
    #pragma unroll
    for (int hh = 0; hh < 2; hh++) {
        int j = hh ? j1 : j0;
        if (j != i) {
            float dt = g_pdent[0][i][j] + g_pdent[1][i][j];
            float dh = g_pdenh[0][i][j] + g_pdenh[1][i][j];
            float l  = g_l[i][j];
            pos_t += (double)(l - logf(dt + 1e-7f));
            pos_h += (double)(l - logf(dh + 1e-7f));
        }
    }

    #pragma unroll
    for (int o = 16; o; o >>= 1) {
        pos_t += __shfl_xor_sync(FULL, pos_t, o);
        pos_h += __shfl_xor_sync(FULL, pos_h, o);
    }
    if (lane == 0) { redt[w] = pos_t; redh[w] = pos_h; }
    __syncthreads();

    if (tid == 0) {
        double at = 0.0, ah = 0.0;
        #pragma unroll
        for (int ww = 0; ww < NWARP; ww++) { at += redt[ww]; ah += redh[ww]; }
        atomicAdd(&g_acc_trans, at);
        atomicAdd(&g_acc_hard,  ah);
        g_row_ticket[i] = 0u;            // reset for next invocation
        __threadfence();
        unsigned ticket = atomicAdd(&g_done, 1u);
        if (ticket == (unsigned)(N - 1)) {
            double vt = atomicAdd(&g_acc_trans, 0.0);
            double vh = atomicAdd(&g_acc_hard,  0.0);
            const double denom = (double)N * (double)(N - 1);
            out[0] = (float)((-vh / denom) + 0.5 * (-vt / denom));
            g_acc_trans = 0.0;
            g_acc_hard  = 0.0;
            g_done      = 0u;
        }
    }
}

extern "C" void kernel_launch(void* const* d_in, const int* in_sizes, int n_in,
                              void* d_out, int out_size) {
    const float* feat   = (const float*)d_in[0];
    const float* rgreen = (const float*)d_in[1];
    const float* rred   = (const float*)d_in[2];
    const float* trans  = (const float*)d_in[3];
    const int*   sym    = (const int*)d_in[4];
    float* out = (float*)d_out;

    rnc_main_kernel<<<2 * N, TPB>>>(feat, rgreen, rred, trans, sym, out);
}

// round 10
// speedup vs baseline: 1.2358x; 1.1604x over previous
#include <cuda_runtime.h>
#include <math.h>

#define N 384
#define D 128
#define TPB 384
#define NWARP (TPB / 32)   // 12
#define FULL 0xFFFFFFFFu

// Persistent accumulators. Zero at load; last block resets after finalizing so
// every invocation (correctness run + each graph replay) starts clean.
__device__ double   g_acc_trans = 0.0;
__device__ double   g_acc_hard  = 0.0;
__device__ unsigned g_done      = 0u;

__global__ __launch_bounds__(TPB) void rnc_main_kernel(
    const float* __restrict__ feat,   // [N, D]
    const float* __restrict__ rgreen, // [N, 3]
    const float* __restrict__ rred,   // [N, 3]
    const float* __restrict__ trans,  // [N, 3]
    const int*   __restrict__ sym,    // [N, 1]
    float*       __restrict__ out)
{
    __shared__ __align__(16) float fi[D];
    __shared__ __align__(16) float td_sh[N];
    __shared__ __align__(16) float rd_sh[N];
    __shared__ __align__(16) float l_sh[N];
    __shared__ __align__(16) float e_sh[N];
    __shared__ __align__(16) float rd_p[N];   // rd permuted to sorted order
    __shared__ __align__(16) float e_p[N];    // e  permuted to sorted order
    __shared__ unsigned long long key_sh[512];
    __shared__ float  wsum[NWARP];
    __shared__ double redt[NWARP];
    __shared__ double redh[NWARP];

    const int i    = blockIdx.x;
    const int tid  = threadIdx.x;
    const int lane = tid & 31;
    const int w    = tid >> 5;

    // ---- stage row-i feature vector (coalesced) ----
    if (tid < D / 4)
        reinterpret_cast<float4*>(fi)[tid] =
            reinterpret_cast<const float4*>(feat + i * D)[tid];
    __syncthreads();

    // ---- feature sq-dist -> logits/e (warp-coop, coalesced; 12 warps x 32 rows)
    {
        const float4 a = reinterpret_cast<const float4*>(fi)[lane];
        const int rowbase = w * 32;              // lane r keeps row rowbase+r == tid
        float sq = 0.f;
        #pragma unroll 4
        for (int r = 0; r < 32; r++) {
            float4 b = reinterpret_cast<const float4*>(feat + (rowbase + r) * D)[lane];
            float d0 = a.x - b.x, d1 = a.y - b.y, d2 = a.z - b.z, d3 = a.w - b.w;
            float p = d0 * d0;
            p = fmaf(d1, d1, p);
            p = fmaf(d2, d2, p);
            p = fmaf(d3, d3, p);
            #pragma unroll
            for (int o = 16; o; o >>= 1) p += __shfl_xor_sync(FULL, p, o);
            if (lane == r) sq = p;
        }
        // rowmax of logits is exactly 0 (logit_ii = -0.5*sqrt(0) bit-exactly,
        // all others <= 0) -> no max pass needed.
        float l = -((sq > 0.f) ? sqrtf(sq) : 0.f) * 0.5f;
        l_sh[tid] = l;
        e_sh[tid] = (tid == i) ? 0.f : expf(l);  // zero diag == offdiag einsum
    }

    // ---- label diffs for j = tid ----
    {
        const int j = tid;
        float ti0 = trans[i*3+0], ti1 = trans[i*3+1], ti2 = trans[i*3+2]; // bcast
        float d0 = ti0 - trans[j*3+0];
        float d1 = ti1 - trans[j*3+1];
        float d2 = ti2 - trans[j*3+2];
        float a0 = fabsf(d0), a1 = fabsf(d1), a2 = fabsf(d2);
        float s = ((a0 < 1.f) ? 0.5f*d0*d0 : a0 - 0.5f)
                + ((a1 < 1.f) ? 0.5f*d1*d1 : a1 - 0.5f)
                + ((a2 < 1.f) ? 0.5f*d2*d2 : a2 - 0.5f);
        float tdv = s * (1.0f / 3.0f);
        td_sh[j] = tdv;

        const float EPSC = 1e-8f;
        float gi0 = rgreen[i*3+0], gi1 = rgreen[i*3+1], gi2 = rgreen[i*3+2];
        float ngi = fmaxf(sqrtf(gi0*gi0 + gi1*gi1 + gi2*gi2), EPSC);
        float gj0 = rgreen[j*3+0], gj1 = rgreen[j*3+1], gj2 = rgreen[j*3+2];
        float ngj = fmaxf(sqrtf(gj0*gj0 + gj1*gj1 + gj2*gj2), EPSC);
        float gd  = 1.0f - (gi0*gj0 + gi1*gj1 + gi2*gj2) / (ngi * ngj);

        float ri0 = rred[i*3+0], ri1 = rred[i*3+1], ri2 = rred[i*3+2];
        float nri = fmaxf(sqrtf(ri0*ri0 + ri1*ri1 + ri2*ri2), EPSC);
        float rj0 = rred[j*3+0], rj1 = rred[j*3+1], rj2 = rred[j*3+2];
        float nrj = fmaxf(sqrtf(rj0*rj0 + rj1*rj1 + rj2*rj2), EPSC);
        float rdd = 1.0f - (ri0*rj0 + ri1*rj1 + ri2*rj2) / (nri * nrj);

        bool psym = (sym[i] == 1) || (sym[j] == 1);
        rd_sh[j] = psym ? gd : gd + rdd;

        // sort key: td bits (non-negative float -> order-preserving) | index
        key_sh[tid] = ((unsigned long long)__float_as_uint(tdv) << 32)
                      | (unsigned long long)j;
        if (tid < 512 - N) key_sh[N + tid] = 0xFFFFFFFFFFFFFFFFULL;  // pad to top
    }
    __syncthreads();

    // ---- bitonic sort 512 keys ascending (256 worker threads, 45 stages) ----
    for (int kk = 2; kk <= 512; kk <<= 1) {
        for (int jj = kk >> 1; jj > 0; jj >>= 1) {
            if (tid < 256) {
                int low = tid & (jj - 1);
                int idx = ((tid - low) << 1) + low;
                int par = idx + jj;
                bool asc = ((idx & kk) == 0);
                unsigned long long a = key_sh[idx];
                unsigned long long b = key_sh[par];
                if ((a > b) == asc) { key_sh[idx] = b; key_sh[par] = a; }
            }
            __syncthreads();
        }
    }

    // ---- gather rd/e into sorted order; thread tid owns sorted position p=tid
    const int   oj     = (int)(key_sh[tid] & 0xFFFFFFFFULL);  // original j
    const float rd_own = rd_sh[oj];
    const float e_own  = e_sh[oj];
    rd_p[tid] = rd_own;
    e_p[tid]  = e_own;
    __syncthreads();

    // ---- suffix sum of e_p: den_trans[p] = sum_{q >= p} e_p[q] ----
    float den_t;
    {
        float pre = e_own;   // inclusive prefix within warp
        #pragma unroll
        for (int o = 1; o < 32; o <<= 1) {
            float t = __shfl_up_sync(FULL, pre, o);
            if (lane >= o) pre += t;
        }
        float wtot = __shfl_sync(FULL, pre, 31);
        if (lane == 31) wsum[w] = pre;
        __syncthreads();
        float tail = 0.f;
        #pragma unroll
        for (int ww = 0; ww < NWARP; ww++) if (ww > w) tail += wsum[ww];
        den_t = tail + wtot - (pre - e_own);   // tail + in-warp inclusive suffix
    }

    // ---- den_hard[p] = sum_{q >= p, rd_p[q] >= rd_own} e_p[q] ----
    // Warp w covers positions [32w, 32w+32); loop q-groups from 8w.
    float dh = 0.f, dh2 = 0.f;
    {
        const float4* rd4 = reinterpret_cast<const float4*>(rd_p);
        const float4* e4  = reinterpret_cast<const float4*>(e_p);
        // peel: first 8 groups need the q >= p check
        #pragma unroll
        for (int g = 0; g < 8; g++) {
            int gg = 8 * w + g;
            float4 rk = rd4[gg];
            float4 ek = e4[gg];
            int qb = 4 * gg;
            if (qb + 0 >= tid && rd_own <= rk.x) dh  += ek.x;
            if (qb + 1 >= tid && rd_own <= rk.y) dh2 += ek.y;
            if (qb + 2 >= tid && rd_own <= rk.z) dh  += ek.z;
            if (qb + 3 >= tid && rd_own <= rk.w) dh2 += ek.w;
        }
        // remainder: q >= p guaranteed
        #pragma unroll 4
        for (int gg = 8 * w + 8; gg < N / 4; gg++) {
            float4 rk = rd4[gg];
            float4 ek = e4[gg];
            if (rd_own <= rk.x) dh  += ek.x;
            if (rd_own <= rk.y) dh2 += ek.y;
            if (rd_own <= rk.z) dh  += ek.z;
            if (rd_own <= rk.w) dh2 += ek.w;
        }
    }
    float den_h = dh + dh2;

    // ---- per-j log terms (skip diagonal j == i) ----
    double pos_t = 0.0, pos_h = 0.0;
    if (oj != i) {
        float l = l_sh[oj];
        pos_t = (double)(l - logf(den_t + 1e-7f));
        pos_h = (double)(l - logf(den_h + 1e-7f));
    }

    // ---- block reduction (double) ----
    #pragma unroll
    for (int o = 16; o; o >>= 1) {
        pos_t += __shfl_xor_sync(FULL, pos_t, o);
        pos_h += __shfl_xor_sync(FULL, pos_h, o);
    }
    if (lane == 0) { redt[w] = pos_t; redh[w] = pos_h; }
    __syncthreads();

    // ---- global accumulation + last-block finalize (self-resetting) ----
    if (tid == 0) {
        double at = 0.0, ah = 0.0;
        #pragma unroll
        for (int ww = 0; ww < NWARP; ww++) { at += redt[ww]; ah += redh[ww]; }
        atomicAdd(&g_acc_trans, at);
        atomicAdd(&g_acc_hard,  ah);
        __threadfence();
        unsigned ticket = atomicAdd(&g_done, 1u);
        if (ticket == (unsigned)(N - 1)) {
            double vt = atomicAdd(&g_acc_trans, 0.0);
            double vh = atomicAdd(&g_acc_hard,  0.0);
            const double denom = (double)N * (double)(N - 1);
            out[0] = (float)((-vh / denom) + 0.5 * (-vt / denom));
            g_acc_trans = 0.0;
            g_acc_hard  = 0.0;
            g_done      = 0u;
        }
    }
}

extern "C" void kernel_launch(void* const* d_in, const int* in_sizes, int n_in,
                              void* d_out, int out_size) {
    const float* feat   = (const float*)d_in[0];
    const float* rgreen = (const float*)d_in[1];
    const float* rred   = (const float*)d_in[2];
    const float* trans  = (const float*)d_in[3];
    const int*   sym    = (const int*)d_in[4];
    float* out = (float*)d_out;

    rnc_main_kernel<<<N, TPB>>>(feat, rgreen, rred, trans, sym, out);
}

// round 11
// speedup vs baseline: 1.2566x; 1.0168x over previous
#include <cuda_runtime.h>
#include <math.h>

#define N 384
#define D 128
#define TPB 512            // 16 warps; sort width 512 (128 +inf pads)
#define NWARP (TPB / 32)
#define FULL 0xFFFFFFFFu

// Persistent accumulators. Zero at load; last block resets after finalizing so
// every invocation (correctness run + each graph replay) starts clean.
__device__ double   g_acc_trans = 0.0;
__device__ double   g_acc_hard  = 0.0;
__device__ unsigned g_done      = 0u;

__global__ __launch_bounds__(TPB) void rnc_main_kernel(
    const float* __restrict__ feat,   // [N, D]
    const float* __restrict__ rgreen, // [N, 3]
    const float* __restrict__ rred,   // [N, 3]
    const float* __restrict__ trans,  // [N, 3]
    const int*   __restrict__ sym,    // [N, 1]
    float*       __restrict__ out)
{
    __shared__ __align__(16) float fi[D];
    __shared__ __align__(16) float td_sh[N];
    __shared__ __align__(16) float rd_sh[N];
    __shared__ __align__(16) float l_sh[N];
    __shared__ __align__(16) float e_sh[N];
    __shared__ __align__(16) float rd_p[N];   // rd permuted to sorted order
    __shared__ __align__(16) float e_p[N];    // e  permuted to sorted order
    __shared__ __align__(16) unsigned long long key_sh[TPB];
    __shared__ float  wsum[NWARP];
    __shared__ double redt[NWARP];
    __shared__ double redh[NWARP];

    const int i    = blockIdx.x;
    const int tid  = threadIdx.x;
    const int lane = tid & 31;
    const int w    = tid >> 5;

    // ---- stage row-i feature vector (coalesced) ----
    if (tid < D / 4)
        reinterpret_cast<float4*>(fi)[tid] =
            reinterpret_cast<const float4*>(feat + i * D)[tid];
    __syncthreads();

    // ---- feature sq-dist -> logits/e: 16 warps x 24 rows, warp-coop coalesced
    {
        const float4 a = reinterpret_cast<const float4*>(fi)[lane];
        const int rowbase = w * 24;
        float sq = 0.f;
        #pragma unroll 4
        for (int r = 0; r < 24; r++) {
            float4 b = reinterpret_cast<const float4*>(feat + (rowbase + r) * D)[lane];
            float d0 = a.x - b.x, d1 = a.y - b.y, d2 = a.z - b.z, d3 = a.w - b.w;
            float p = d0 * d0;
            p = fmaf(d1, d1, p);
            p = fmaf(d2, d2, p);
            p = fmaf(d3, d3, p);
            #pragma unroll
            for (int o = 16; o; o >>= 1) p += __shfl_xor_sync(FULL, p, o);
            if (lane == r) sq = p;
        }
        if (lane < 24) {
            // rowmax of logits is exactly 0 (logit_ii = -0.5*sqrt(0) bit-exact,
            // all others <= 0) -> no max pass needed.
            int row = rowbase + lane;
            float l = -((sq > 0.f) ? sqrtf(sq) : 0.f) * 0.5f;
            l_sh[row] = l;
            e_sh[row] = (row == i) ? 0.f : expf(l);  // zero diag == offdiag
        }
    }

    // ---- label diffs for j = tid (< N); build sort key ----
    unsigned long long key = 0xFFFFFFFFFFFFFFFFULL;   // +inf pad for tid >= N
    if (tid < N) {
        const int j = tid;
        float ti0 = trans[i*3+0], ti1 = trans[i*3+1], ti2 = trans[i*3+2]; // bcast
        float d0 = ti0 - trans[j*3+0];
        float d1 = ti1 - trans[j*3+1];
        float d2 = ti2 - trans[j*3+2];
        float a0 = fabsf(d0), a1 = fabsf(d1), a2 = fabsf(d2);
        float s = ((a0 < 1.f) ? 0.5f*d0*d0 : a0 - 0.5f)
                + ((a1 < 1.f) ? 0.5f*d1*d1 : a1 - 0.5f)
                + ((a2 < 1.f) ? 0.5f*d2*d2 : a2 - 0.5f);
        float tdv = s * (1.0f / 3.0f);
        td_sh[j] = tdv;

        const float EPSC = 1e-8f;
        float gi0 = rgreen[i*3+0], gi1 = rgreen[i*3+1], gi2 = rgreen[i*3+2];
        float ngi = fmaxf(sqrtf(gi0*gi0 + gi1*gi1 + gi2*gi2), EPSC);
        float gj0 = rgreen[j*3+0], gj1 = rgreen[j*3+1], gj2 = rgreen[j*3+2];
        float ngj = fmaxf(sqrtf(gj0*gj0 + gj1*gj1 + gj2*gj2), EPSC);
        float gd  = 1.0f - (gi0*gj0 + gi1*gj1 + gi2*gj2) / (ngi * ngj);

        float ri0 = rred[i*3+0], ri1 = rred[i*3+1], ri2 = rred[i*3+2];
        float nri = fmaxf(sqrtf(ri0*ri0 + ri1*ri1 + ri2*ri2), EPSC);
        float rj0 = rred[j*3+0], rj1 = rred[j*3+1], rj2 = rred[j*3+2];
        float nrj = fmaxf(sqrtf(rj0*rj0 + rj1*rj1 + rj2*rj2), EPSC);
        float rdd = 1.0f - (ri0*rj0 + ri1*rj1 + ri2*rj2) / (nri * nrj);

        bool psym = (sym[i] == 1) || (sym[j] == 1);
        rd_sh[j] = psym ? gd : gd + rdd;

        // key: td bits (non-negative float -> order-preserving) | index
        key = ((unsigned long long)__float_as_uint(tdv) << 32)
              | (unsigned long long)j;
    }

    // ---- hybrid bitonic sort, 512 register-held keys, ascending ----
    // jj < 32: intra-warp via shfl (no barrier). jj >= 32: via smem (2 barriers).
    for (int kk = 2; kk <= TPB; kk <<= 1) {
        for (int jj = kk >> 1; jj > 0; jj >>= 1) {
            unsigned long long other;
            if (jj >= 32) {
                __syncthreads();
                key_sh[tid] = key;
                __syncthreads();
                other = key_sh[tid ^ jj];
            } else {
                other = __shfl_xor_sync(FULL, key, jj);
            }
            bool up     = ((tid & kk) == 0);
            bool takeLo = (up == ((tid & jj) == 0));
            bool repl   = takeLo ? (other < key) : (other > key);
            key = repl ? other : key;
        }
    }
    __syncthreads();   // protect rd_p/e_p writes below vs earlier key_sh reads

    // ---- gather rd/e into sorted order; thread tid owns sorted position p=tid
    // Pads (+inf keys) sit at positions >= N, held by threads >= N.
    int   oj = -1;
    float rd_own = 0.f, e_own = 0.f;
    if (tid < N) {
        oj     = (int)(key & 0xFFFFFFFFULL);
        rd_own = rd_sh[oj];
        e_own  = e_sh[oj];
        rd_p[tid] = rd_own;
        e_p[tid]  = e_own;
    }
    __syncthreads();

    // ---- suffix sum of e_p: den_trans[p] = sum_{q >= p} e_p[q] ----
    float den_t;
    {
        float pre = e_own;   // inclusive prefix within warp (pads contribute 0)
        #pragma unroll
        for (int o = 1; o < 32; o <<= 1) {
            float t = __shfl_up_sync(FULL, pre, o);
            if (lane >= o) pre += t;
        }
        float wtot = __shfl_sync(FULL, pre, 31);
        if (lane == 31) wsum[w] = pre;
        __syncthreads();
        float tail = 0.f;
        #pragma unroll
        for (int ww = 0; ww < NWARP; ww++) if (ww > w) tail += wsum[ww];
        den_t = tail + wtot - (pre - e_own);   // tail + in-warp inclusive suffix
    }

    // ---- den_hard[p] = sum_{q >= p, rd_p[q] >= rd_own} e_p[q] ----
    // Warps 0..11 cover positions [32w, 32w+32); q-groups from 8w.
    float den_h = 0.f;
    if (w < 12) {
        float dh = 0.f, dh2 = 0.f;
        const float4* rd4 = reinterpret_cast<const float4*>(rd_p);
        const float4* e4  = reinterpret_cast<const float4*>(e_p);
        // peel: first 8 groups need the q >= p check
        #pragma unroll
        for (int g = 0; g < 8; g++) {
            int gg = 8 * w + g;
            float4 rk = rd4[gg];
            float4 ek = e4[gg];
            int qb = 4 * gg;
            if (qb + 0 >= tid && rd_own <= rk.x) dh  += ek.x;
            if (qb + 1 >= tid && rd_own <= rk.y) dh2 += ek.y;
            if (qb + 2 >= tid && rd_own <= rk.z) dh  += ek.z;
            if (qb + 3 >= tid && rd_own <= rk.w) dh2 += ek.w;
        }
        // remainder: q >= p guaranteed
        #pragma unroll 4
        for (int gg = 8 * w + 8; gg < N / 4; gg++) {
            float4 rk = rd4[gg];
            float4 ek = e4[gg];
            if (rd_own <= rk.x) dh  += ek.x;
            if (rd_own <= rk.y) dh2 += ek.y;
            if (rd_own <= rk.z) dh  += ek.z;
            if (rd_own <= rk.w) dh2 += ek.w;
        }
        den_h = dh + dh2;
    }

    // ---- per-j log terms (skip diagonal j == i; pads contribute 0) ----
    double pos_t = 0.0, pos_h = 0.0;
    if (tid < N && oj != i) {
        float l = l_sh[oj];
        pos_t = (double)(l - logf(den_t + 1e-7f));
        pos_h = (double)(l - logf(den_h + 1e-7f));
    }

    // ---- block reduction (double) ----
    #pragma unroll
    for (int o = 16; o; o >>= 1) {
        pos_t += __shfl_xor_sync(FULL, pos_t, o);
        pos_h += __shfl_xor_sync(FULL, pos_h, o);
    }
    if (lane == 0) { redt[w] = pos_t; redh[w] = pos_h; }
    __syncthreads();

    // ---- global accumulation + last-block finalize (self-resetting) ----
    if (tid == 0) {
        double at = 0.0, ah = 0.0;
        #pragma unroll
        for (int ww = 0; ww < NWARP; ww++) { at += redt[ww]; ah += redh[ww]; }
        atomicAdd(&g_acc_trans, at);
        atomicAdd(&g_acc_hard,  ah);
        __threadfence();
        unsigned ticket = atomicAdd(&g_done, 1u);
        if (ticket == (unsigned)(N - 1)) {
            double vt = atomicAdd(&g_acc_trans, 0.0);
            double vh = atomicAdd(&g_acc_hard,  0.0);
            const double denom = (double)N * (double)(N - 1);
            out[0] = (float)((-vh / denom) + 0.5 * (-vt / denom));
            g_acc_trans = 0.0;
            g_acc_hard  = 0.0;
            g_done      = 0u;
        }
    }
}

extern "C" void kernel_launch(void* const* d_in, const int* in_sizes, int n_in,
                              void* d_out, int out_size) {
    const float* feat   = (const float*)d_in[0];
    const float* rgreen = (const float*)d_in[1];
    const float* rred   = (const float*)d_in[2];
    const float* trans  = (const float*)d_in[3];
    const int*   sym    = (const int*)d_in[4];
    float* out = (float*)d_out;

    rnc_main_kernel<<<N, TPB>>>(feat, rgreen, rred, trans, sym, out);
}